// round 6
// baseline (speedup 1.0000x reference)
#include <cuda_runtime.h>
#include <cuda_bf16.h>

// Problem dims
#define NB 64
#define TT 512
#define II 512
#define HH 1024
#define OO 512
#define NT (NB*TT)        // 32768
#define NHh (NB*HH)       // 65536 floats per timestep slab

// ---------------- scratch (device globals; no cudaMalloc allowed) -------------
__device__ float g_bufA[TT*NB*HH];   // 128 MB : inp_v -> hs_v (in-place)
__device__ float g_bufB[TT*NB*HH];   // 128 MB : inp_m -> hs_m (in-place)
__device__ float g_bufO[NT*OO];      //  64 MB : out_v
__device__ float g_bufO2[NT*OO];     //  64 MB : out_t
__device__ float g_hx0[HH*NB];       // ping-pong h exchange, [H][N] layout
__device__ float g_hx1[HH*NB];
// producer-consumer flags: [half 0..1][group 0..15], padded by 32 uints
__device__ unsigned g_gflag[32*32];

// ---------------- packed fp32x2 helpers (Blackwell dual-FP32 pipe) ------------
__device__ __forceinline__ unsigned long long dup2(float a) {
    unsigned long long r;
    asm("mov.b64 %0, {%1, %1};" : "=l"(r) : "f"(a));
    return r;
}
__device__ __forceinline__ void fma2(unsigned long long& c, unsigned long long a,
                                     unsigned long long b) {
    asm("fma.rn.f32x2 %0, %1, %2, %0;" : "+l"(c) : "l"(a), "l"(b));
}
__device__ __forceinline__ float lo32(unsigned long long v) {
    return __uint_as_float((unsigned)(v & 0xffffffffull));
}
__device__ __forceinline__ float hi32(unsigned long long v) {
    return __uint_as_float((unsigned)(v >> 32));
}
__device__ __forceinline__ unsigned ld_acquire(const unsigned* p) {
    unsigned v;
    asm volatile("ld.acquire.gpu.global.u32 %0, [%1];" : "=r"(v) : "l"(p));
    return v;
}
__device__ __forceinline__ void red_add_release(unsigned* p, unsigned v) {
    asm volatile("red.add.release.gpu.global.u32 [%0], %1;" :: "l"(p), "r"(v));
}
// fast retanh: tanh(max(x,0)) via ex2.approx + div.approx (rel err ~1e-6)
__device__ __forceinline__ float retanh(float x) {
    float xm = fmaxf(x, 0.0f);
    float p = xm * -2.885390082f;            // -2*log2(e)*x
    float e;
    asm("ex2.approx.f32 %0, %1;" : "=f"(e) : "f"(p));
    return __fdividef(1.0f - e, 1.0f + e);
}

// ======================= SGEMM: C[remap(m)][:] = A[m,:K] @ B[:,K]^T + bias ====
#define BM 128
#define BN 128
#define BK 16

__global__ __launch_bounds__(256, 2) void sgemm_kernel(
    const float* __restrict__ A, const float* __restrict__ B,
    const float* __restrict__ bias1, const float* __restrict__ bias2,
    float* __restrict__ C, int M, int Nc, int K, int D1, int D2, int act)
{
    __shared__ float As[BK][BM + 8];
    __shared__ float Bs[BK][BN + 8];

    const int tid = threadIdx.x;
    const int m0 = blockIdx.y * BM;
    const int j0 = blockIdx.x * BN;
    const int tm = tid >> 4;
    const int tn = tid & 15;
    const int lr = tid >> 2;
    const int lk = (tid & 3) * 4;

    const float* ap0 = A + (size_t)(m0 + lr) * K + lk;
    const float* ap1 = A + (size_t)(m0 + lr + 64) * K + lk;
    const float* bp0 = B + (size_t)(j0 + lr) * K + lk;
    const float* bp1 = B + (size_t)(j0 + lr + 64) * K + lk;

    unsigned long long acc[8][4];
#pragma unroll
    for (int i = 0; i < 8; i++)
#pragma unroll
        for (int j = 0; j < 4; j++) acc[i][j] = 0ull;

    float4 pa0 = *(const float4*)ap0;
    float4 pa1 = *(const float4*)ap1;
    float4 pb0 = *(const float4*)bp0;
    float4 pb1 = *(const float4*)bp1;

    for (int kt = 0; kt < K; kt += BK) {
        As[lk + 0][lr] = pa0.x; As[lk + 1][lr] = pa0.y;
        As[lk + 2][lr] = pa0.z; As[lk + 3][lr] = pa0.w;
        As[lk + 0][lr + 64] = pa1.x; As[lk + 1][lr + 64] = pa1.y;
        As[lk + 2][lr + 64] = pa1.z; As[lk + 3][lr + 64] = pa1.w;
        Bs[lk + 0][lr] = pb0.x; Bs[lk + 1][lr] = pb0.y;
        Bs[lk + 2][lr] = pb0.z; Bs[lk + 3][lr] = pb0.w;
        Bs[lk + 0][lr + 64] = pb1.x; Bs[lk + 1][lr + 64] = pb1.y;
        Bs[lk + 2][lr + 64] = pb1.z; Bs[lk + 3][lr + 64] = pb1.w;
        __syncthreads();

        if (kt + BK < K) {
            pa0 = *(const float4*)(ap0 + kt + BK);
            pa1 = *(const float4*)(ap1 + kt + BK);
            pb0 = *(const float4*)(bp0 + kt + BK);
            pb1 = *(const float4*)(bp1 + kt + BK);
        }

#pragma unroll
        for (int kk = 0; kk < BK; kk++) {
            float a[8];
            *(float4*)&a[0] = *(const float4*)&As[kk][tm * 8];
            *(float4*)&a[4] = *(const float4*)&As[kk][tm * 8 + 4];
            ulonglong2 b01 = *(const ulonglong2*)&Bs[kk][tn * 8];
            ulonglong2 b23 = *(const ulonglong2*)&Bs[kk][tn * 8 + 4];
#pragma unroll
            for (int i = 0; i < 8; i++) {
                unsigned long long ad = dup2(a[i]);
                fma2(acc[i][0], ad, b01.x);
                fma2(acc[i][1], ad, b01.y);
                fma2(acc[i][2], ad, b23.x);
                fma2(acc[i][3], ad, b23.y);
            }
        }
        __syncthreads();
    }

    float bcol[8];
#pragma unroll
    for (int j = 0; j < 8; j++) {
        const int cn = j0 + tn * 8 + j;
        float b = bias1[cn];
        if (bias2) b += bias2[cn];
        bcol[j] = b;
    }
#pragma unroll
    for (int i = 0; i < 8; i++) {
        const int rm = m0 + tm * 8 + i;
        const int orow = (rm % D1) * D2 + (rm / D1);
        float out[8];
#pragma unroll
        for (int j = 0; j < 4; j++) {
            out[2 * j + 0] = lo32(acc[i][j]) + bcol[2 * j + 0];
            out[2 * j + 1] = hi32(acc[i][j]) + bcol[2 * j + 1];
        }
        if (act) {
#pragma unroll
            for (int j = 0; j < 8; j++) out[j] = retanh(out[j]);
        }
        float* cp = C + (size_t)orow * Nc + j0 + tn * 8;
        *(float4*)cp       = *(float4*)&out[0];
        *(float4*)(cp + 4) = *(float4*)&out[4];
    }
}

// ======================= h0 transpose + flag reset ===========================
__global__ __launch_bounds__(512) void transpose_h0(
    const float* __restrict__ h0, float* __restrict__ hx)
{
    const int idx = blockIdx.x * 512 + threadIdx.x;
    const int h = idx >> 6, n = idx & 63;
    hx[idx] = h0[(size_t)n * HH + h];
}

__global__ __launch_bounds__(1024) void reset_flags_kernel() {
    g_gflag[threadIdx.x] = 0u;
}

// ======================= Persistent recurrence kernel =========================
// Grid = 64 CTAs (one per 16-column slice). Each CTA runs BOTH batch halves:
// warps 0-15 = half 0, warps 16-31 = half 1, sharing the Wh slice in SMEM.
// Per-half named barriers keep the halves independent; half 1 starts with a
// seeded skew so its compute fills the other half's wait bubbles (anti-phase).
#define RGRID 64
#define RTHR  1024
// Whs 1024*16 f (64KB) + redU 2*16*32*9 ull (72KB) = 139264 B
#define RSMEM (65536 + 73728)

__global__ __launch_bounds__(RTHR, 1) void recur_kernel(
    float* __restrict__ buf, const float* __restrict__ Wh,
    float* __restrict__ hx0, float* __restrict__ hx1)
{
    extern __shared__ float smem[];
    float* Whs = smem;                                                // [1024][16]
    unsigned long long* redU = (unsigned long long*)(smem + 16384);   // 2*[16][32][9]

    const int tid  = threadIdx.x;
    const int half = tid >> 9;            // batch half 0/1
    const int ltid = tid & 511;
    const int bidh = blockIdx.x;          // column slice 0..63
    const int nb0  = half * 32;
    const int c0   = bidh * 16;

    // Wh slice transposed into SMEM: Whs[k][cl] = Wh[c0+cl][k]  (1024 threads)
    {
        const int cl = tid & 15;
        const int kb = (tid >> 4) * 16;
        const float* wrow = Wh + (size_t)(c0 + cl) * HH + kb;
#pragma unroll
        for (int kk = 0; kk < 16; kk++) Whs[(kb + kk) * 16 + cl] = wrow[kk];
    }
    __syncthreads();   // only full-CTA sync; none inside the loop

    const int wid  = ltid >> 5;           // k-chunk / reduce-c-warp 0..15
    const int lane = ltid & 31;
    const int k0   = wid * 64;
    // reduce/publish mapping: c = lane&15, n = 2*wid + (lane>>4)
    const int cR   = lane & 15;
    const int nR   = 2 * wid + (lane >> 4);

    unsigned long long* redU_h = redU + half * 4608;
    const float* redF = (const float*)redU_h;

    const unsigned* my_wait_flag = &g_gflag[(half * 16 + wid) * 32];
    unsigned* my_post_flag = &g_gflag[(half * 16 + (bidh >> 2)) * 32];
    const unsigned barid = 1 + half;

    // seed anti-phase: half 1 starts ~half a step later
    if (half == 1) {
        unsigned long long s0 = clock64();
        while (clock64() - s0 < 4500ull) {}
    }

    for (int t = 0; t < TT; t++) {
        const float* hp = ((t & 1) ? hx1 : hx0) + (size_t)k0 * NB + nb0 + lane;
        float*       hn = ((t & 1) ? hx0 : hx1);
        float* outp = buf + (size_t)t * NHh + (size_t)(nb0 + nR) * HH + (c0 + cR);
        const float x_pre = __ldcg(outp);   // step-t input, load before wait

        // wait until my 4 source slices have published step t-1 (counter = 4t)
        {
            const unsigned tgt = 4u * (unsigned)t;
            while (ld_acquire(my_wait_flag) < tgt) __nanosleep(20);
        }

        unsigned long long acc[8];
#pragma unroll
        for (int j = 0; j < 8; j++) acc[j] = 0ull;

        // software pipeline, prefetch distance 2 (3-deep rolling buffer)
        float hbuf[3][8];
#pragma unroll
        for (int j = 0; j < 8; j++) hbuf[0][j] = __ldcg(hp + (size_t)j * NB);
#pragma unroll
        for (int j = 0; j < 8; j++) hbuf[1][j] = __ldcg(hp + (size_t)(8 + j) * NB);

#pragma unroll
        for (int g = 0; g < 8; g++) {
            if (g + 2 < 8) {
#pragma unroll
                for (int j = 0; j < 8; j++)
                    hbuf[(g + 2) % 3][j] =
                        __ldcg(hp + (size_t)((g + 2) * 8 + j) * NB);
            }
#pragma unroll
            for (int j = 0; j < 8; j++) {
                const unsigned long long ad = dup2(hbuf[g % 3][j]);
                const float* wk = &Whs[(k0 + g * 8 + j) * 16];
                ulonglong2 w0 = *(const ulonglong2*)(wk + 0);
                ulonglong2 w1 = *(const ulonglong2*)(wk + 4);
                ulonglong2 w2 = *(const ulonglong2*)(wk + 8);
                ulonglong2 w3 = *(const ulonglong2*)(wk + 12);
                fma2(acc[0], ad, w0.x); fma2(acc[1], ad, w0.y);
                fma2(acc[2], ad, w1.x); fma2(acc[3], ad, w1.y);
                fma2(acc[4], ad, w2.x); fma2(acc[5], ad, w2.y);
                fma2(acc[6], ad, w3.x); fma2(acc[7], ad, w3.y);
            }
        }

        // partials -> redU_h[wid][lane][0..7]
        {
            unsigned long long* rp = &redU_h[(size_t)(wid * 32 + lane) * 9];
#pragma unroll
            for (int j = 0; j < 8; j++) rp[j] = acc[j];
        }
        asm volatile("bar.sync %0, 512;" :: "r"(barid) : "memory");   // A

        // reduce 16 k-chunks for output (n=nR, c=cR), publish directly
        float s = 0.0f;
#pragma unroll
        for (int w = 0; w < 16; w++)
            s += redF[(w * 32 + nR) * 18 + cR];
        const float v = retanh(s + x_pre);
        *outp = v;                                   // [T,N,H] for the GEMM
        hn[(size_t)(c0 + cR) * NB + nb0 + nR] = v;   // [H][N] for next step
        asm volatile("bar.sync %0, 512;" :: "r"(barid) : "memory");   // B

        // announce: this slice-half published step t
        if (ltid == 0) red_add_release(my_post_flag, 1u);
    }
}

// ======================= launcher ==============================================
static void launch_gemm(const float* A, const float* B, const float* b1,
                        const float* b2, float* C, int M, int Nc, int K,
                        int D1, int D2, int act)
{
    dim3 grid(Nc / BN, M / BM);
    sgemm_kernel<<<grid, 256>>>(A, B, b1, b2, C, M, Nc, K, D1, D2, act);
}

extern "C" void kernel_launch(void* const* d_in, const int* in_sizes, int n_in,
                              void* d_out, int out_size)
{
    const float* data = (const float*)d_in[0];
    const float* h0_v = (const float*)d_in[1];
    const float* h0_m = (const float*)d_in[2];
    const float* Wi   = (const float*)d_in[3];
    const float* bi   = (const float*)d_in[4];
    const float* Wh   = (const float*)d_in[5];
    const float* bh   = (const float*)d_in[6];
    const float* Wo   = (const float*)d_in[7];
    const float* bo   = (const float*)d_in[8];
    const float* Wt   = (const float*)d_in[9];
    const float* bt   = (const float*)d_in[10];
    const float* Wi2  = (const float*)d_in[11];
    const float* bi2  = (const float*)d_in[12];
    const float* Wh2  = (const float*)d_in[13];
    const float* bh2  = (const float*)d_in[14];
    const float* Wo2  = (const float*)d_in[15];
    const float* bo2  = (const float*)d_in[16];
    float* out = (float*)d_out;

    float *bufA, *bufB, *bufO, *bufO2, *hx0, *hx1;
    cudaGetSymbolAddress((void**)&bufA,  g_bufA);
    cudaGetSymbolAddress((void**)&bufB,  g_bufB);
    cudaGetSymbolAddress((void**)&bufO,  g_bufO);
    cudaGetSymbolAddress((void**)&bufO2, g_bufO2);
    cudaGetSymbolAddress((void**)&hx0,   g_hx0);
    cudaGetSymbolAddress((void**)&hx1,   g_hx1);

    cudaFuncSetAttribute(recur_kernel,
                         cudaFuncAttributeMaxDynamicSharedMemorySize, RSMEM);

    // 1) inp_v = data @ Wi^T + (bi + bh) -> [T,N,H]
    launch_gemm(data, Wi, bi, bh, bufA, NT, HH, II, TT, NB, 0);
    // 2) visual recurrence
    transpose_h0<<<128, 512>>>(h0_v, hx0);
    reset_flags_kernel<<<1, 1024>>>();
    recur_kernel<<<RGRID, RTHR, RSMEM>>>(bufA, Wh, hx0, hx1);
    // 3) out_v = hs_v @ Wo^T + bo -> [N,T,O]
    launch_gemm(bufA, Wo, bo, nullptr, bufO, NT, OO, HH, NB, TT, 0);
    // 4) out_t = retanh(out_v @ Wt^T + bt)
    launch_gemm(bufO, Wt, bt, nullptr, bufO2, NT, OO, OO, NT, 1, 1);
    // 5) inp_m = out_t @ Wi2^T + (bi2 + bh2) -> [T,N,H]
    launch_gemm(bufO2, Wi2, bi2, bh2, bufB, NT, HH, OO, TT, NB, 0);
    // 6) motor recurrence
    transpose_h0<<<128, 512>>>(h0_m, hx0);
    reset_flags_kernel<<<1, 1024>>>();
    recur_kernel<<<RGRID, RTHR, RSMEM>>>(bufB, Wh2, hx0, hx1);
    // 7) out_m = hs_m @ Wo2^T + bo2 -> [N,T,O]
    launch_gemm(bufB, Wo2, bo2, nullptr, out, NT, OO, HH, NB, TT, 0);
}

// round 7
// speedup vs baseline: 1.4719x; 1.4719x over previous
#include <cuda_runtime.h>
#include <cuda_bf16.h>

// Problem dims
#define NB 64
#define TT 512
#define II 512
#define HH 1024
#define OO 512
#define NT (NB*TT)        // 32768
#define NHh (NB*HH)       // 65536 floats per timestep slab

// ---------------- scratch (device globals; no cudaMalloc allowed) -------------
__device__ float g_bufA[TT*NB*HH];   // 128 MB : inp_v -> hs_v (in-place)
__device__ float g_bufB[TT*NB*HH];   // 128 MB : inp_m -> hs_m (in-place)
__device__ float g_bufO[NT*OO];      //  64 MB : out_v
__device__ float g_bufO2[NT*OO];     //  64 MB : out_t
__device__ float g_hx0[HH*NB];       // ping-pong h exchange, [H][N] layout
__device__ float g_hx1[HH*NB];
// producer-consumer flags: [half 0..1][group 0..15], padded by 32 uints
__device__ unsigned g_gflag[32*32];

// ---------------- packed fp32x2 helpers (Blackwell dual-FP32 pipe) ------------
__device__ __forceinline__ unsigned long long dup2(float a) {
    unsigned long long r;
    asm("mov.b64 %0, {%1, %1};" : "=l"(r) : "f"(a));
    return r;
}
__device__ __forceinline__ void fma2(unsigned long long& c, unsigned long long a,
                                     unsigned long long b) {
    asm("fma.rn.f32x2 %0, %1, %2, %0;" : "+l"(c) : "l"(a), "l"(b));
}
__device__ __forceinline__ float lo32(unsigned long long v) {
    return __uint_as_float((unsigned)(v & 0xffffffffull));
}
__device__ __forceinline__ float hi32(unsigned long long v) {
    return __uint_as_float((unsigned)(v >> 32));
}
__device__ __forceinline__ unsigned ld_acquire(const unsigned* p) {
    unsigned v;
    asm volatile("ld.acquire.gpu.global.u32 %0, [%1];" : "=r"(v) : "l"(p));
    return v;
}
__device__ __forceinline__ void red_add_release(unsigned* p, unsigned v) {
    asm volatile("red.add.release.gpu.global.u32 [%0], %1;" :: "l"(p), "r"(v));
}
// fast retanh: tanh(max(x,0)) via ex2.approx + div.approx (rel err ~1e-6)
__device__ __forceinline__ float retanh(float x) {
    float xm = fmaxf(x, 0.0f);
    float p = xm * -2.885390082f;            // -2*log2(e)*x
    float e;
    asm("ex2.approx.f32 %0, %1;" : "=f"(e) : "f"(p));
    return __fdividef(1.0f - e, 1.0f + e);
}

// ======================= SGEMM: C[remap(m)][:] = A[m,:K] @ B[:,K]^T + bias ====
// Double-buffered SMEM: stage tile k+1 while computing tile k (1 barrier/tile).
#define BM 128
#define BN 128
#define BK 16

__global__ __launch_bounds__(256, 2) void sgemm_kernel(
    const float* __restrict__ A, const float* __restrict__ B,
    const float* __restrict__ bias1, const float* __restrict__ bias2,
    float* __restrict__ C, int M, int Nc, int K, int D1, int D2, int act)
{
    __shared__ float As[2][BK][BM + 8];
    __shared__ float Bs[2][BK][BN + 8];

    const int tid = threadIdx.x;
    const int m0 = blockIdx.y * BM;
    const int j0 = blockIdx.x * BN;
    const int tm = tid >> 4;
    const int tn = tid & 15;
    const int lr = tid >> 2;
    const int lk = (tid & 3) * 4;

    const float* ap0 = A + (size_t)(m0 + lr) * K + lk;
    const float* ap1 = A + (size_t)(m0 + lr + 64) * K + lk;
    const float* bp0 = B + (size_t)(j0 + lr) * K + lk;
    const float* bp1 = B + (size_t)(j0 + lr + 64) * K + lk;

    unsigned long long acc[8][4];
#pragma unroll
    for (int i = 0; i < 8; i++)
#pragma unroll
        for (int j = 0; j < 4; j++) acc[i][j] = 0ull;

    // preload + stage tile 0 into buffer 0
    {
        float4 pa0 = *(const float4*)ap0;
        float4 pa1 = *(const float4*)ap1;
        float4 pb0 = *(const float4*)bp0;
        float4 pb1 = *(const float4*)bp1;
        As[0][lk + 0][lr] = pa0.x; As[0][lk + 1][lr] = pa0.y;
        As[0][lk + 2][lr] = pa0.z; As[0][lk + 3][lr] = pa0.w;
        As[0][lk + 0][lr + 64] = pa1.x; As[0][lk + 1][lr + 64] = pa1.y;
        As[0][lk + 2][lr + 64] = pa1.z; As[0][lk + 3][lr + 64] = pa1.w;
        Bs[0][lk + 0][lr] = pb0.x; Bs[0][lk + 1][lr] = pb0.y;
        Bs[0][lk + 2][lr] = pb0.z; Bs[0][lk + 3][lr] = pb0.w;
        Bs[0][lk + 0][lr + 64] = pb1.x; Bs[0][lk + 1][lr + 64] = pb1.y;
        Bs[0][lk + 2][lr + 64] = pb1.z; Bs[0][lk + 3][lr + 64] = pb1.w;
    }
    __syncthreads();

    int cur = 0;
    for (int kt = 0; kt < K; kt += BK) {
        float4 pa0, pa1, pb0, pb1;
        const bool more = (kt + BK < K);
        if (more) {   // next tile's LDGs fly during this tile's compute
            pa0 = *(const float4*)(ap0 + kt + BK);
            pa1 = *(const float4*)(ap1 + kt + BK);
            pb0 = *(const float4*)(bp0 + kt + BK);
            pb1 = *(const float4*)(bp1 + kt + BK);
        }

#pragma unroll
        for (int kk = 0; kk < BK; kk++) {
            float a[8];
            *(float4*)&a[0] = *(const float4*)&As[cur][kk][tm * 8];
            *(float4*)&a[4] = *(const float4*)&As[cur][kk][tm * 8 + 4];
            ulonglong2 b01 = *(const ulonglong2*)&Bs[cur][kk][tn * 8];
            ulonglong2 b23 = *(const ulonglong2*)&Bs[cur][kk][tn * 8 + 4];
#pragma unroll
            for (int i = 0; i < 8; i++) {
                unsigned long long ad = dup2(a[i]);
                fma2(acc[i][0], ad, b01.x);
                fma2(acc[i][1], ad, b01.y);
                fma2(acc[i][2], ad, b23.x);
                fma2(acc[i][3], ad, b23.y);
            }
        }

        if (more) {
            const int nxt = cur ^ 1;
            As[nxt][lk + 0][lr] = pa0.x; As[nxt][lk + 1][lr] = pa0.y;
            As[nxt][lk + 2][lr] = pa0.z; As[nxt][lk + 3][lr] = pa0.w;
            As[nxt][lk + 0][lr + 64] = pa1.x; As[nxt][lk + 1][lr + 64] = pa1.y;
            As[nxt][lk + 2][lr + 64] = pa1.z; As[nxt][lk + 3][lr + 64] = pa1.w;
            Bs[nxt][lk + 0][lr] = pb0.x; Bs[nxt][lk + 1][lr] = pb0.y;
            Bs[nxt][lk + 2][lr] = pb0.z; Bs[nxt][lk + 3][lr] = pb0.w;
            Bs[nxt][lk + 0][lr + 64] = pb1.x; Bs[nxt][lk + 1][lr + 64] = pb1.y;
            Bs[nxt][lk + 2][lr + 64] = pb1.z; Bs[nxt][lk + 3][lr + 64] = pb1.w;
            __syncthreads();
            cur = nxt;
        }
    }

    float bcol[8];
#pragma unroll
    for (int j = 0; j < 8; j++) {
        const int cn = j0 + tn * 8 + j;
        float b = bias1[cn];
        if (bias2) b += bias2[cn];
        bcol[j] = b;
    }
#pragma unroll
    for (int i = 0; i < 8; i++) {
        const int rm = m0 + tm * 8 + i;
        const int orow = (rm % D1) * D2 + (rm / D1);
        float out[8];
#pragma unroll
        for (int j = 0; j < 4; j++) {
            out[2 * j + 0] = lo32(acc[i][j]) + bcol[2 * j + 0];
            out[2 * j + 1] = hi32(acc[i][j]) + bcol[2 * j + 1];
        }
        if (act) {
#pragma unroll
            for (int j = 0; j < 8; j++) out[j] = retanh(out[j]);
        }
        float* cp = C + (size_t)orow * Nc + j0 + tn * 8;
        *(float4*)cp       = *(float4*)&out[0];
        *(float4*)(cp + 4) = *(float4*)&out[4];
    }
}

// ======================= h0 transpose + flag reset ===========================
__global__ __launch_bounds__(512) void transpose_h0(
    const float* __restrict__ h0, float* __restrict__ hx)
{
    const int idx = blockIdx.x * 512 + threadIdx.x;
    const int h = idx >> 6, n = idx & 63;
    hx[idx] = h0[(size_t)n * HH + h];
}

__global__ __launch_bounds__(1024) void reset_flags_kernel() {
    g_gflag[threadIdx.x] = 0u;
}

// ======================= Persistent recurrence kernel =========================
// Grid = 128 CTAs = 2 batch halves x 64 column-slices of 16 (one SM each).
// 16 warps each own a 64-wide k-chunk (= flag group wid), compute all 16
// columns via f32x2. Direct reduce->publish mapping (c=lane&15, n=2w+(lane>>4)).
#define RGRID 128
#define RTHR  512
// Whs 1024*16 f (64KB) + redU 4608 ull (36KB)
#define RSMEM ((16384 + 9216) * 4)

__global__ __launch_bounds__(RTHR) void recur_kernel(
    float* __restrict__ buf, const float* __restrict__ Wh,
    float* __restrict__ hx0, float* __restrict__ hx1)
{
    extern __shared__ float smem[];
    float* Whs = smem;                                                // [1024][16]
    unsigned long long* redU = (unsigned long long*)(smem + 16384);   // [16][32][9]

    const int tid  = threadIdx.x;
    const int bidb = blockIdx.x >> 6;     // batch half
    const int bidh = blockIdx.x & 63;     // column slice
    const int nb0  = bidb * 32;
    const int c0   = bidh * 16;

    // Wh slice transposed into SMEM: Whs[k][cl] = Wh[c0+cl][k]
    {
        const int cl = tid & 15;
        const int kb = (tid >> 4) * 32;
        const float* wrow = Wh + (size_t)(c0 + cl) * HH + kb;
#pragma unroll
        for (int kk = 0; kk < 32; kk++) Whs[(kb + kk) * 16 + cl] = wrow[kk];
    }
    __syncthreads();

    const int wid  = tid >> 5;            // k-chunk / flag group 0..15
    const int lane = tid & 31;            // batch row within half
    const int k0   = wid * 64;
    // reduce/publish mapping: c = lane&15, n = 2*wid + (lane>>4)
    const int cR   = lane & 15;
    const int nR   = 2 * wid + (lane >> 4);
    const float* redF = (const float*)redU;

    const unsigned* my_wait_flag = &g_gflag[(bidb * 16 + wid) * 32];
    unsigned* my_post_flag = &g_gflag[(bidb * 16 + (bidh >> 2)) * 32];

    for (int t = 0; t < TT; t++) {
        const float* hp = ((t & 1) ? hx1 : hx0) + (size_t)k0 * NB + nb0 + lane;
        float*       hn = ((t & 1) ? hx0 : hx1);
        float* outp = buf + (size_t)t * NHh + (size_t)(nb0 + nR) * HH + (c0 + cR);
        const float x_pre = __ldcg(outp);   // step-independent: load before wait

        // wait until my 4 source slices have published step t-1 (counter = 4t)
        {
            const unsigned tgt = 4u * (unsigned)t;
            while (ld_acquire(my_wait_flag) < tgt) __nanosleep(20);
        }

        unsigned long long acc[8];
#pragma unroll
        for (int j = 0; j < 8; j++) acc[j] = 0ull;

        // software pipeline, prefetch distance 2 (3-deep rolling buffer)
        float hbuf[3][8];
#pragma unroll
        for (int j = 0; j < 8; j++) hbuf[0][j] = __ldcg(hp + (size_t)j * NB);
#pragma unroll
        for (int j = 0; j < 8; j++) hbuf[1][j] = __ldcg(hp + (size_t)(8 + j) * NB);

#pragma unroll
        for (int g = 0; g < 8; g++) {
            if (g + 2 < 8) {
#pragma unroll
                for (int j = 0; j < 8; j++)
                    hbuf[(g + 2) % 3][j] =
                        __ldcg(hp + (size_t)((g + 2) * 8 + j) * NB);
            }
#pragma unroll
            for (int j = 0; j < 8; j++) {
                const unsigned long long ad = dup2(hbuf[g % 3][j]);
                const float* wk = &Whs[(k0 + g * 8 + j) * 16];
                ulonglong2 w0 = *(const ulonglong2*)(wk + 0);
                ulonglong2 w1 = *(const ulonglong2*)(wk + 4);
                ulonglong2 w2 = *(const ulonglong2*)(wk + 8);
                ulonglong2 w3 = *(const ulonglong2*)(wk + 12);
                fma2(acc[0], ad, w0.x); fma2(acc[1], ad, w0.y);
                fma2(acc[2], ad, w1.x); fma2(acc[3], ad, w1.y);
                fma2(acc[4], ad, w2.x); fma2(acc[5], ad, w2.y);
                fma2(acc[6], ad, w3.x); fma2(acc[7], ad, w3.y);
            }
        }

        // partials -> redU[wid][lane][0..7]
        {
            unsigned long long* rp = &redU[(size_t)(wid * 32 + lane) * 9];
#pragma unroll
            for (int j = 0; j < 8; j++) rp[j] = acc[j];
        }
        __syncthreads();   // A

        // reduce 16 k-chunks for (n=nR, c=cR); publish directly
        float s = 0.0f;
#pragma unroll
        for (int w = 0; w < 16; w++)
            s += redF[(w * 32 + nR) * 18 + cR];
        const float v = retanh(s + x_pre);
        *outp = v;                                   // [T,N,H] for the GEMM
        hn[(size_t)(c0 + cR) * NB + nb0 + nR] = v;   // [H][N] for next step
        __syncthreads();   // B

        // announce: this slice published step t
        if (tid == 0) red_add_release(my_post_flag, 1u);
    }
}

// ======================= launcher ==============================================
static void launch_gemm(const float* A, const float* B, const float* b1,
                        const float* b2, float* C, int M, int Nc, int K,
                        int D1, int D2, int act)
{
    dim3 grid(Nc / BN, M / BM);
    sgemm_kernel<<<grid, 256>>>(A, B, b1, b2, C, M, Nc, K, D1, D2, act);
}

extern "C" void kernel_launch(void* const* d_in, const int* in_sizes, int n_in,
                              void* d_out, int out_size)
{
    const float* data = (const float*)d_in[0];
    const float* h0_v = (const float*)d_in[1];
    const float* h0_m = (const float*)d_in[2];
    const float* Wi   = (const float*)d_in[3];
    const float* bi   = (const float*)d_in[4];
    const float* Wh   = (const float*)d_in[5];
    const float* bh   = (const float*)d_in[6];
    const float* Wo   = (const float*)d_in[7];
    const float* bo   = (const float*)d_in[8];
    const float* Wt   = (const float*)d_in[9];
    const float* bt   = (const float*)d_in[10];
    const float* Wi2  = (const float*)d_in[11];
    const float* bi2  = (const float*)d_in[12];
    const float* Wh2  = (const float*)d_in[13];
    const float* bh2  = (const float*)d_in[14];
    const float* Wo2  = (const float*)d_in[15];
    const float* bo2  = (const float*)d_in[16];
    float* out = (float*)d_out;

    float *bufA, *bufB, *bufO, *bufO2, *hx0, *hx1;
    cudaGetSymbolAddress((void**)&bufA,  g_bufA);
    cudaGetSymbolAddress((void**)&bufB,  g_bufB);
    cudaGetSymbolAddress((void**)&bufO,  g_bufO);
    cudaGetSymbolAddress((void**)&bufO2, g_bufO2);
    cudaGetSymbolAddress((void**)&hx0,   g_hx0);
    cudaGetSymbolAddress((void**)&hx1,   g_hx1);

    cudaFuncSetAttribute(recur_kernel,
                         cudaFuncAttributeMaxDynamicSharedMemorySize, RSMEM);

    // 1) inp_v = data @ Wi^T + (bi + bh) -> [T,N,H]
    launch_gemm(data, Wi, bi, bh, bufA, NT, HH, II, TT, NB, 0);
    // 2) visual recurrence
    transpose_h0<<<128, 512>>>(h0_v, hx0);
    reset_flags_kernel<<<1, 1024>>>();
    recur_kernel<<<RGRID, RTHR, RSMEM>>>(bufA, Wh, hx0, hx1);
    // 3) out_v = hs_v @ Wo^T + bo -> [N,T,O]
    launch_gemm(bufA, Wo, bo, nullptr, bufO, NT, OO, HH, NB, TT, 0);
    // 4) out_t = retanh(out_v @ Wt^T + bt)
    launch_gemm(bufO, Wt, bt, nullptr, bufO2, NT, OO, OO, NT, 1, 1);
    // 5) inp_m = out_t @ Wi2^T + (bi2 + bh2) -> [T,N,H]
    launch_gemm(bufO2, Wi2, bi2, bh2, bufB, NT, HH, OO, TT, NB, 0);
    // 6) motor recurrence
    transpose_h0<<<128, 512>>>(h0_m, hx0);
    reset_flags_kernel<<<1, 1024>>>();
    recur_kernel<<<RGRID, RTHR, RSMEM>>>(bufB, Wh2, hx0, hx1);
    // 7) out_m = hs_m @ Wo2^T + bo2 -> [N,T,O]
    launch_gemm(bufB, Wo2, bo2, nullptr, out, NT, OO, HH, NB, TT, 0);
}

// round 8
// speedup vs baseline: 1.5006x; 1.0195x over previous
#include <cuda_runtime.h>
#include <cuda_bf16.h>

// Problem dims
#define NB 64
#define TT 512
#define II 512
#define HH 1024
#define OO 512
#define NT (NB*TT)        // 32768
#define NHh (NB*HH)       // 65536 floats per timestep slab

// ---------------- scratch (device globals; no cudaMalloc allowed) -------------
__device__ float g_bufA[TT*NB*HH];   // 128 MB : inp_v -> hs_v (in-place)
__device__ float g_bufB[TT*NB*HH];   // 128 MB : inp_m -> hs_m (in-place)
__device__ float g_bufO[NT*OO];      //  64 MB : out_v
__device__ float g_bufO2[NT*OO];     //  64 MB : out_t
__device__ float g_hx0[HH*NB];       // ping-pong h exchange, [H][N] layout
__device__ float g_hx1[HH*NB];
// producer-consumer flags: [half 0..1][group 0..15], padded by 32 uints
__device__ unsigned g_gflag[32*32];

// ---------------- packed fp32x2 helpers (Blackwell dual-FP32 pipe) ------------
__device__ __forceinline__ unsigned long long dup2(float a) {
    unsigned long long r;
    asm("mov.b64 %0, {%1, %1};" : "=l"(r) : "f"(a));
    return r;
}
__device__ __forceinline__ void fma2(unsigned long long& c, unsigned long long a,
                                     unsigned long long b) {
    asm("fma.rn.f32x2 %0, %1, %2, %0;" : "+l"(c) : "l"(a), "l"(b));
}
__device__ __forceinline__ float lo32(unsigned long long v) {
    return __uint_as_float((unsigned)(v & 0xffffffffull));
}
__device__ __forceinline__ float hi32(unsigned long long v) {
    return __uint_as_float((unsigned)(v >> 32));
}
__device__ __forceinline__ unsigned ld_acquire(const unsigned* p) {
    unsigned v;
    asm volatile("ld.acquire.gpu.global.u32 %0, [%1];" : "=r"(v) : "l"(p));
    return v;
}
__device__ __forceinline__ void red_add_release(unsigned* p, unsigned v) {
    asm volatile("red.add.release.gpu.global.u32 [%0], %1;" :: "l"(p), "r"(v));
}
// fast retanh: tanh(max(x,0)) via ex2.approx + div.approx (rel err ~1e-6)
__device__ __forceinline__ float retanh(float x) {
    float xm = fmaxf(x, 0.0f);
    float p = xm * -2.885390082f;            // -2*log2(e)*x
    float e;
    asm("ex2.approx.f32 %0, %1;" : "=f"(e) : "f"(p));
    return __fdividef(1.0f - e, 1.0f + e);
}

// ======================= SGEMM: C[remap(m)][:] = A[m,:K] @ B[:,K]^T + bias ====
// Double-buffered SMEM: stage tile k+1 while computing tile k (1 barrier/tile).
#define BM 128
#define BN 128
#define BK 16

__global__ __launch_bounds__(256, 2) void sgemm_kernel(
    const float* __restrict__ A, const float* __restrict__ B,
    const float* __restrict__ bias1, const float* __restrict__ bias2,
    float* __restrict__ C, int M, int Nc, int K, int D1, int D2, int act)
{
    __shared__ float As[2][BK][BM + 8];
    __shared__ float Bs[2][BK][BN + 8];

    const int tid = threadIdx.x;
    const int m0 = blockIdx.y * BM;
    const int j0 = blockIdx.x * BN;
    const int tm = tid >> 4;
    const int tn = tid & 15;
    const int lr = tid >> 2;
    const int lk = (tid & 3) * 4;

    const float* ap0 = A + (size_t)(m0 + lr) * K + lk;
    const float* ap1 = A + (size_t)(m0 + lr + 64) * K + lk;
    const float* bp0 = B + (size_t)(j0 + lr) * K + lk;
    const float* bp1 = B + (size_t)(j0 + lr + 64) * K + lk;

    unsigned long long acc[8][4];
#pragma unroll
    for (int i = 0; i < 8; i++)
#pragma unroll
        for (int j = 0; j < 4; j++) acc[i][j] = 0ull;

    // preload + stage tile 0 into buffer 0
    {
        float4 pa0 = *(const float4*)ap0;
        float4 pa1 = *(const float4*)ap1;
        float4 pb0 = *(const float4*)bp0;
        float4 pb1 = *(const float4*)bp1;
        As[0][lk + 0][lr] = pa0.x; As[0][lk + 1][lr] = pa0.y;
        As[0][lk + 2][lr] = pa0.z; As[0][lk + 3][lr] = pa0.w;
        As[0][lk + 0][lr + 64] = pa1.x; As[0][lk + 1][lr + 64] = pa1.y;
        As[0][lk + 2][lr + 64] = pa1.z; As[0][lk + 3][lr + 64] = pa1.w;
        Bs[0][lk + 0][lr] = pb0.x; Bs[0][lk + 1][lr] = pb0.y;
        Bs[0][lk + 2][lr] = pb0.z; Bs[0][lk + 3][lr] = pb0.w;
        Bs[0][lk + 0][lr + 64] = pb1.x; Bs[0][lk + 1][lr + 64] = pb1.y;
        Bs[0][lk + 2][lr + 64] = pb1.z; Bs[0][lk + 3][lr + 64] = pb1.w;
    }
    __syncthreads();

    int cur = 0;
    for (int kt = 0; kt < K; kt += BK) {
        float4 pa0, pa1, pb0, pb1;
        const bool more = (kt + BK < K);
        if (more) {   // next tile's LDGs fly during this tile's compute
            pa0 = *(const float4*)(ap0 + kt + BK);
            pa1 = *(const float4*)(ap1 + kt + BK);
            pb0 = *(const float4*)(bp0 + kt + BK);
            pb1 = *(const float4*)(bp1 + kt + BK);
        }

#pragma unroll
        for (int kk = 0; kk < BK; kk++) {
            float a[8];
            *(float4*)&a[0] = *(const float4*)&As[cur][kk][tm * 8];
            *(float4*)&a[4] = *(const float4*)&As[cur][kk][tm * 8 + 4];
            ulonglong2 b01 = *(const ulonglong2*)&Bs[cur][kk][tn * 8];
            ulonglong2 b23 = *(const ulonglong2*)&Bs[cur][kk][tn * 8 + 4];
#pragma unroll
            for (int i = 0; i < 8; i++) {
                unsigned long long ad = dup2(a[i]);
                fma2(acc[i][0], ad, b01.x);
                fma2(acc[i][1], ad, b01.y);
                fma2(acc[i][2], ad, b23.x);
                fma2(acc[i][3], ad, b23.y);
            }
        }

        if (more) {
            const int nxt = cur ^ 1;
            As[nxt][lk + 0][lr] = pa0.x; As[nxt][lk + 1][lr] = pa0.y;
            As[nxt][lk + 2][lr] = pa0.z; As[nxt][lk + 3][lr] = pa0.w;
            As[nxt][lk + 0][lr + 64] = pa1.x; As[nxt][lk + 1][lr + 64] = pa1.y;
            As[nxt][lk + 2][lr + 64] = pa1.z; As[nxt][lk + 3][lr + 64] = pa1.w;
            Bs[nxt][lk + 0][lr] = pb0.x; Bs[nxt][lk + 1][lr] = pb0.y;
            Bs[nxt][lk + 2][lr] = pb0.z; Bs[nxt][lk + 3][lr] = pb0.w;
            Bs[nxt][lk + 0][lr + 64] = pb1.x; Bs[nxt][lk + 1][lr + 64] = pb1.y;
            Bs[nxt][lk + 2][lr + 64] = pb1.z; Bs[nxt][lk + 3][lr + 64] = pb1.w;
            __syncthreads();
            cur = nxt;
        }
    }

    float bcol[8];
#pragma unroll
    for (int j = 0; j < 8; j++) {
        const int cn = j0 + tn * 8 + j;
        float b = bias1[cn];
        if (bias2) b += bias2[cn];
        bcol[j] = b;
    }
#pragma unroll
    for (int i = 0; i < 8; i++) {
        const int rm = m0 + tm * 8 + i;
        const int orow = (rm % D1) * D2 + (rm / D1);
        float out[8];
#pragma unroll
        for (int j = 0; j < 4; j++) {
            out[2 * j + 0] = lo32(acc[i][j]) + bcol[2 * j + 0];
            out[2 * j + 1] = hi32(acc[i][j]) + bcol[2 * j + 1];
        }
        if (act) {
#pragma unroll
            for (int j = 0; j < 8; j++) out[j] = retanh(out[j]);
        }
        float* cp = C + (size_t)orow * Nc + j0 + tn * 8;
        *(float4*)cp       = *(float4*)&out[0];
        *(float4*)(cp + 4) = *(float4*)&out[4];
    }
}

// ======================= h0 transpose + flag reset ===========================
__global__ __launch_bounds__(512) void transpose_h0(
    const float* __restrict__ h0, float* __restrict__ hx)
{
    const int idx = blockIdx.x * 512 + threadIdx.x;
    const int h = idx >> 6, n = idx & 63;
    hx[idx] = h0[(size_t)n * HH + h];
}

__global__ __launch_bounds__(1024) void reset_flags_kernel() {
    g_gflag[threadIdx.x] = 0u;
}

// ======================= Persistent recurrence kernel =========================
// Grid = 128 CTAs = 2 batch halves x 64 column-slices of 16 (one SM each).
// 16 warps each own a 64-wide k-chunk (= flag group wid), compute all 16
// columns via f32x2. Direct reduce->publish mapping (c=lane&15, n=2w+(lane>>4)).
#define RGRID 128
#define RTHR  512
// Whs 1024*16 f (64KB) + redU 4608 ull (36KB)
#define RSMEM ((16384 + 9216) * 4)

__global__ __launch_bounds__(RTHR) void recur_kernel(
    float* __restrict__ buf, const float* __restrict__ Wh,
    float* __restrict__ hx0, float* __restrict__ hx1)
{
    extern __shared__ float smem[];
    float* Whs = smem;                                                // [1024][16]
    unsigned long long* redU = (unsigned long long*)(smem + 16384);   // [16][32][9]

    const int tid  = threadIdx.x;
    const int bidb = blockIdx.x >> 6;     // batch half
    const int bidh = blockIdx.x & 63;     // column slice
    const int nb0  = bidb * 32;
    const int c0   = bidh * 16;

    // Wh slice transposed into SMEM: Whs[k][cl] = Wh[c0+cl][k]
    {
        const int cl = tid & 15;
        const int kb = (tid >> 4) * 32;
        const float* wrow = Wh + (size_t)(c0 + cl) * HH + kb;
#pragma unroll
        for (int kk = 0; kk < 32; kk++) Whs[(kb + kk) * 16 + cl] = wrow[kk];
    }
    __syncthreads();

    const int wid  = tid >> 5;            // k-chunk / flag group 0..15
    const int lane = tid & 31;            // batch row within half
    const int k0   = wid * 64;
    // reduce/publish mapping: c = lane&15, n = 2*wid + (lane>>4)
    const int cR   = lane & 15;
    const int nR   = 2 * wid + (lane >> 4);
    const float* redF = (const float*)redU;

    const unsigned* my_wait_flag = &g_gflag[(bidb * 16 + wid) * 32];
    unsigned* my_post_flag = &g_gflag[(bidb * 16 + (bidh >> 2)) * 32];

    for (int t = 0; t < TT; t++) {
        const float* hp = ((t & 1) ? hx1 : hx0) + (size_t)k0 * NB + nb0 + lane;
        float*       hn = ((t & 1) ? hx0 : hx1);
        float* outp = buf + (size_t)t * NHh + (size_t)(nb0 + nR) * HH + (c0 + cR);
        const float x_pre = __ldcg(outp);   // step-independent: load before wait

        // wait until my 4 source slices have published step t-1 (counter = 4t)
        {
            const unsigned tgt = 4u * (unsigned)t;
            while (ld_acquire(my_wait_flag) < tgt) __nanosleep(20);
        }

        unsigned long long acc[8];
#pragma unroll
        for (int j = 0; j < 8; j++) acc[j] = 0ull;

        // software pipeline, prefetch distance 2 (3-deep rolling buffer)
        float hbuf[3][8];
#pragma unroll
        for (int j = 0; j < 8; j++) hbuf[0][j] = __ldcg(hp + (size_t)j * NB);
#pragma unroll
        for (int j = 0; j < 8; j++) hbuf[1][j] = __ldcg(hp + (size_t)(8 + j) * NB);

#pragma unroll
        for (int g = 0; g < 8; g++) {
            if (g + 2 < 8) {
#pragma unroll
                for (int j = 0; j < 8; j++)
                    hbuf[(g + 2) % 3][j] =
                        __ldcg(hp + (size_t)((g + 2) * 8 + j) * NB);
            }
#pragma unroll
            for (int j = 0; j < 8; j++) {
                const unsigned long long ad = dup2(hbuf[g % 3][j]);
                const float* wk = &Whs[(k0 + g * 8 + j) * 16];
                ulonglong2 w0 = *(const ulonglong2*)(wk + 0);
                ulonglong2 w1 = *(const ulonglong2*)(wk + 4);
                ulonglong2 w2 = *(const ulonglong2*)(wk + 8);
                ulonglong2 w3 = *(const ulonglong2*)(wk + 12);
                fma2(acc[0], ad, w0.x); fma2(acc[1], ad, w0.y);
                fma2(acc[2], ad, w1.x); fma2(acc[3], ad, w1.y);
                fma2(acc[4], ad, w2.x); fma2(acc[5], ad, w2.y);
                fma2(acc[6], ad, w3.x); fma2(acc[7], ad, w3.y);
            }
        }

        // partials -> redU[wid][lane][0..7]
        {
            unsigned long long* rp = &redU[(size_t)(wid * 32 + lane) * 9];
#pragma unroll
            for (int j = 0; j < 8; j++) rp[j] = acc[j];
        }
        __syncthreads();   // A

        // reduce 16 k-chunks for (n=nR, c=cR); publish directly
        float s = 0.0f;
#pragma unroll
        for (int w = 0; w < 16; w++)
            s += redF[(w * 32 + nR) * 18 + cR];
        const float v = retanh(s + x_pre);
        *outp = v;                                   // [T,N,H] for the GEMM
        hn[(size_t)(c0 + cR) * NB + nb0 + nR] = v;   // [H][N] for next step
        __syncthreads();   // B

        // announce: this slice published step t
        if (tid == 0) red_add_release(my_post_flag, 1u);
    }
}

// ======================= launcher ==============================================
static void launch_gemm(const float* A, const float* B, const float* b1,
                        const float* b2, float* C, int M, int Nc, int K,
                        int D1, int D2, int act)
{
    dim3 grid(Nc / BN, M / BM);
    sgemm_kernel<<<grid, 256>>>(A, B, b1, b2, C, M, Nc, K, D1, D2, act);
}

extern "C" void kernel_launch(void* const* d_in, const int* in_sizes, int n_in,
                              void* d_out, int out_size)
{
    const float* data = (const float*)d_in[0];
    const float* h0_v = (const float*)d_in[1];
    const float* h0_m = (const float*)d_in[2];
    const float* Wi   = (const float*)d_in[3];
    const float* bi   = (const float*)d_in[4];
    const float* Wh   = (const float*)d_in[5];
    const float* bh   = (const float*)d_in[6];
    const float* Wo   = (const float*)d_in[7];
    const float* bo   = (const float*)d_in[8];
    const float* Wt   = (const float*)d_in[9];
    const float* bt   = (const float*)d_in[10];
    const float* Wi2  = (const float*)d_in[11];
    const float* bi2  = (const float*)d_in[12];
    const float* Wh2  = (const float*)d_in[13];
    const float* bh2  = (const float*)d_in[14];
    const float* Wo2  = (const float*)d_in[15];
    const float* bo2  = (const float*)d_in[16];
    float* out = (float*)d_out;

    float *bufA, *bufB, *bufO, *bufO2, *hx0, *hx1;
    cudaGetSymbolAddress((void**)&bufA,  g_bufA);
    cudaGetSymbolAddress((void**)&bufB,  g_bufB);
    cudaGetSymbolAddress((void**)&bufO,  g_bufO);
    cudaGetSymbolAddress((void**)&bufO2, g_bufO2);
    cudaGetSymbolAddress((void**)&hx0,   g_hx0);
    cudaGetSymbolAddress((void**)&hx1,   g_hx1);

    cudaFuncSetAttribute(recur_kernel,
                         cudaFuncAttributeMaxDynamicSharedMemorySize, RSMEM);

    // 1) inp_v = data @ Wi^T + (bi + bh) -> [T,N,H]
    launch_gemm(data, Wi, bi, bh, bufA, NT, HH, II, TT, NB, 0);
    // 2) visual recurrence
    transpose_h0<<<128, 512>>>(h0_v, hx0);
    reset_flags_kernel<<<1, 1024>>>();
    recur_kernel<<<RGRID, RTHR, RSMEM>>>(bufA, Wh, hx0, hx1);
    // 3) out_v = hs_v @ Wo^T + bo -> [N,T,O]
    launch_gemm(bufA, Wo, bo, nullptr, bufO, NT, OO, HH, NB, TT, 0);
    // 4) out_t = retanh(out_v @ Wt^T + bt)
    launch_gemm(bufO, Wt, bt, nullptr, bufO2, NT, OO, OO, NT, 1, 1);
    // 5) inp_m = out_t @ Wi2^T + (bi2 + bh2) -> [T,N,H]
    launch_gemm(bufO2, Wi2, bi2, bh2, bufB, NT, HH, OO, TT, NB, 0);
    // 6) motor recurrence
    transpose_h0<<<128, 512>>>(h0_m, hx0);
    reset_flags_kernel<<<1, 1024>>>();
    recur_kernel<<<RGRID, RTHR, RSMEM>>>(bufB, Wh2, hx0, hx1);
    // 7) out_m = hs_m @ Wo2^T + bo2 -> [N,T,O]
    launch_gemm(bufB, Wo2, bo2, nullptr, out, NT, OO, HH, NB, TT, 0);
}